// round 8
// baseline (speedup 1.0000x reference)
#include <cuda_runtime.h>
#include <cstdint>

#define NN 100000
#define EE 1600000

// ---------------- scratch (no allocations allowed) ----------------
__device__ float g_h1[(size_t)NN * 128];
__device__ float g_out1[(size_t)NN * 128];
__device__ float g_h2[(size_t)NN * 64];
__device__ float g_as[NN];
__device__ float g_ad[NN];
__device__ int   g_deg[NN];
__device__ int   g_rowptr[NN + 1];
__device__ int   g_cursor[NN];
__device__ int   g_bsum[128];
__device__ int   g_colsrc[EE];
__device__ int   g_is64;

// ---------------- edge dtype sniff ----------------
__global__ void detect_edge_dtype(const int* __restrict__ ei32) {
    if (threadIdx.x == 0 && blockIdx.x == 0) {
        int all_hi_zero = 1;
        for (int i = 0; i < 256; i++)
            if (ei32[2 * i + 1] != 0) { all_hi_zero = 0; break; }
        g_is64 = all_hi_zero;
    }
}

__device__ __forceinline__ int load_edge(const void* ei, int i, int half) {
    int v;
    if (g_is64) v = (int)((const long long*)ei)[(size_t)half * EE + i];
    else        v = ((const int*)ei)[(size_t)half * EE + i];
    return min(max(v, 0), NN - 1);
}

__global__ __launch_bounds__(256) void histo_edges(const void* __restrict__ ei) {
    int i = blockIdx.x * 256 + threadIdx.x;
    if (i >= EE) return;
    atomicAdd(&g_deg[load_edge(ei, i, 1)], 1);
}

// ---------------- exclusive scan ----------------
__global__ __launch_bounds__(1024) void scan1() {
    __shared__ int sh[1024];
    int i = blockIdx.x * 1024 + threadIdx.x;
    int v = (i < NN) ? g_deg[i] : 0;
    sh[threadIdx.x] = v;
    __syncthreads();
    #pragma unroll
    for (int o = 1; o < 1024; o <<= 1) {
        int t = (threadIdx.x >= o) ? sh[threadIdx.x - o] : 0;
        __syncthreads();
        sh[threadIdx.x] += t;
        __syncthreads();
    }
    if (i < NN) g_rowptr[i] = sh[threadIdx.x] - v;
    if (threadIdx.x == 1023) g_bsum[blockIdx.x] = sh[1023];
}

__global__ void scan2(int nblk) {
    __shared__ int sh[128];
    int v = (threadIdx.x < nblk) ? g_bsum[threadIdx.x] : 0;
    sh[threadIdx.x] = v;
    __syncthreads();
    #pragma unroll
    for (int o = 1; o < 128; o <<= 1) {
        int t = (threadIdx.x >= o) ? sh[threadIdx.x - o] : 0;
        __syncthreads();
        sh[threadIdx.x] += t;
        __syncthreads();
    }
    if (threadIdx.x < nblk) g_bsum[threadIdx.x] = sh[threadIdx.x] - v;
}

__global__ __launch_bounds__(256) void scan3() {
    int i = blockIdx.x * 256 + threadIdx.x;
    if (i < NN) {
        int rp = g_rowptr[i] + g_bsum[i >> 10];
        g_rowptr[i] = rp;
        g_cursor[i] = rp;
    }
    if (i == NN) g_rowptr[NN] = EE;
}

__global__ __launch_bounds__(256) void fill_csr(const void* __restrict__ ei) {
    int e = blockIdx.x * 256 + threadIdx.x;
    if (e >= EE) return;
    int s = load_edge(ei, e, 0);
    int d = load_edge(ei, e, 1);
    int pos = atomicAdd(&g_cursor[d], 1);
    g_colsrc[pos] = s;
}

// ---------------- tensor-core GEMM (3xTF32, in-register split) ----------
// H[m][n] = sum_k X'[m][k] W[k][n]   (X' = relu(X+bin) if RELU_BIAS)
// g_as[m] = H[m].a_src ; g_ad[m] = H[m].a_dst
// Natural-layout smem (As[m][k] row-major, Bs[n][k] k-major), conflict-free
// LDS.32 fragment fetch, hi/lo tf32 split in registers.
// Fragment<->lane mapping identical to R6 (validated: rel_err 1.8e-6).

__device__ __forceinline__ uint32_t f2tf32(float x) {
    uint32_t r;
    asm("cvt.rna.tf32.f32 %0, %1;" : "=r"(r) : "f"(x));
    return r;
}
__device__ __forceinline__ uint32_t tf32lo(float x, uint32_t hi) {
    return f2tf32(x - __uint_as_float(hi));
}

#define MMA_TF32(d, a0, a1, a2, a3, b0, b1)                                \
    asm volatile("mma.sync.aligned.m16n8k8.row.col.f32.tf32.tf32.f32 "     \
        "{%0,%1,%2,%3}, {%4,%5,%6,%7}, {%8,%9}, {%0,%1,%2,%3};"            \
        : "+f"(d[0]), "+f"(d[1]), "+f"(d[2]), "+f"(d[3])                   \
        : "r"(a0), "r"(a1), "r"(a2), "r"(a3), "r"(b0), "r"(b1))

template <int BN, bool RELU_BIAS>
__global__ __launch_bounds__(BN * 2) void gemm_tc(
    const float* __restrict__ X, const float* __restrict__ W,
    const float* __restrict__ bin,
    const float* __restrict__ avs, const float* __restrict__ avd,
    float* __restrict__ H)
{
    constexpr int K = 128, BM = 64, KC = 64, KP = 68;   // KP: padded k stride
    constexpr int NW = BN / 32;                          // n-warps: 4 or 2
    constexpr int THREADS = BN * 2;                      // 256 or 128

    extern __shared__ float sm[];
    float* As = sm;                  // [BM][KP]
    float* Bs = sm + BM * KP;        // [BN][KP]  (k-major)

    const int tid = threadIdx.x, lane = tid & 31, wid = tid >> 5;
    const int wm = wid & 1, wn = wid >> 1;
    const int m0 = blockIdx.x * BM;
    const int lr = lane >> 2, kq = lane & 3;

    float acc[2][4][4];
    #pragma unroll
    for (int mt = 0; mt < 2; mt++)
        #pragma unroll
        for (int nt = 0; nt < 4; nt++)
            #pragma unroll
            for (int c = 0; c < 4; c++) acc[mt][nt][c] = 0.f;

    #pragma unroll
    for (int kc = 0; kc < 2; kc++) {
        __syncthreads();
        // ---- stage A (straight float4 rows, zero-fill tail) ----
        #pragma unroll
        for (int it = tid; it < BM * 16; it += THREADS) {
            int r = it >> 4, c4 = it & 15;
            float4 v = make_float4(0.f, 0.f, 0.f, 0.f);
            if (m0 + r < NN) {
                v = ((const float4*)X)[(size_t)(m0 + r) * (K / 4) + kc * 16 + c4];
                if constexpr (RELU_BIAS) {
                    float4 bb = ((const float4*)bin)[kc * 16 + c4];
                    v.x = fmaxf(v.x + bb.x, 0.f);
                    v.y = fmaxf(v.y + bb.y, 0.f);
                    v.z = fmaxf(v.z + bb.z, 0.f);
                    v.w = fmaxf(v.w + bb.w, 0.f);
                }
            }
            *(float4*)&As[r * KP + c4 * 4] = v;
        }
        // ---- stage B transposed: Bs[n][k] <- W[kc*64+k][n] ----
        #pragma unroll
        for (int it = tid; it < KC * (BN / 4); it += THREADS) {
            int k = it / (BN / 4), n4 = it % (BN / 4);
            float4 v = ((const float4*)W)[(size_t)(kc * KC + k) * (BN / 4) + n4];
            Bs[(n4 * 4 + 0) * KP + k] = v.x;
            Bs[(n4 * 4 + 1) * KP + k] = v.y;
            Bs[(n4 * 4 + 2) * KP + k] = v.z;
            Bs[(n4 * 4 + 3) * KP + k] = v.w;
        }
        __syncthreads();
        // ---- mainloop ----
        #pragma unroll
        for (int k8 = 0; k8 < 8; k8++) {
            int k0 = k8 * 8;
            uint32_t ah[2][4], al[2][4];
            #pragma unroll
            for (int mt = 0; mt < 2; mt++) {
                int base = (wm * 32 + mt * 16 + lr) * KP + k0 + kq;
                float a0 = As[base];
                float a1 = As[base + 8 * KP];
                float a2 = As[base + 4];
                float a3 = As[base + 8 * KP + 4];
                ah[mt][0] = f2tf32(a0); al[mt][0] = tf32lo(a0, ah[mt][0]);
                ah[mt][1] = f2tf32(a1); al[mt][1] = tf32lo(a1, ah[mt][1]);
                ah[mt][2] = f2tf32(a2); al[mt][2] = tf32lo(a2, ah[mt][2]);
                ah[mt][3] = f2tf32(a3); al[mt][3] = tf32lo(a3, ah[mt][3]);
            }
            #pragma unroll
            for (int nt = 0; nt < 4; nt++) {
                int bb = (wn * 32 + nt * 8 + lr) * KP + k0 + kq;
                float b0 = Bs[bb];
                float b1 = Bs[bb + 4];
                uint32_t bh0 = f2tf32(b0), bl0 = tf32lo(b0, bh0);
                uint32_t bh1 = f2tf32(b1), bl1 = tf32lo(b1, bh1);
                #pragma unroll
                for (int mt = 0; mt < 2; mt++) {
                    MMA_TF32(acc[mt][nt], ah[mt][0], ah[mt][1], ah[mt][2], ah[mt][3], bh0, bh1);
                    MMA_TF32(acc[mt][nt], al[mt][0], al[mt][1], al[mt][2], al[mt][3], bh0, bh1);
                    MMA_TF32(acc[mt][nt], ah[mt][0], ah[mt][1], ah[mt][2], ah[mt][3], bl0, bl1);
                }
            }
        }
    }

    // ---- epilogue: H stores + a_src/a_dst logit dots ----
    float sp[2][2], dp[2][2];   // [mt][rowgroup]
    #pragma unroll
    for (int mt = 0; mt < 2; mt++)
        sp[mt][0] = sp[mt][1] = dp[mt][0] = dp[mt][1] = 0.f;

    #pragma unroll
    for (int mt = 0; mt < 2; mt++) {
        int rA = m0 + wm * 32 + mt * 16 + lr;
        int rB = rA + 8;
        #pragma unroll
        for (int nt = 0; nt < 4; nt++) {
            int c = wn * 32 + nt * 8 + kq * 2;
            float s0 = __ldg(&avs[c]), s1 = __ldg(&avs[c + 1]);
            float d0 = __ldg(&avd[c]), d1 = __ldg(&avd[c + 1]);
            sp[mt][0] += acc[mt][nt][0] * s0 + acc[mt][nt][1] * s1;
            dp[mt][0] += acc[mt][nt][0] * d0 + acc[mt][nt][1] * d1;
            sp[mt][1] += acc[mt][nt][2] * s0 + acc[mt][nt][3] * s1;
            dp[mt][1] += acc[mt][nt][2] * d0 + acc[mt][nt][3] * d1;
            if (rA < NN)
                *(float2*)&H[(size_t)rA * BN + c] = make_float2(acc[mt][nt][0], acc[mt][nt][1]);
            if (rB < NN)
                *(float2*)&H[(size_t)rB * BN + c] = make_float2(acc[mt][nt][2], acc[mt][nt][3]);
        }
    }
    // quad-reduce (lanes kq 0..3 share rows)
    #pragma unroll
    for (int o = 1; o <= 2; o <<= 1)
        #pragma unroll
        for (int mt = 0; mt < 2; mt++) {
            sp[mt][0] += __shfl_xor_sync(0xffffffffu, sp[mt][0], o);
            dp[mt][0] += __shfl_xor_sync(0xffffffffu, dp[mt][0], o);
            sp[mt][1] += __shfl_xor_sync(0xffffffffu, sp[mt][1], o);
            dp[mt][1] += __shfl_xor_sync(0xffffffffu, dp[mt][1], o);
        }

    __syncthreads();                    // smem reuse: ep[BM][NW][2]
    float* ep = sm;
    if (kq == 0) {
        #pragma unroll
        for (int mt = 0; mt < 2; mt++) {
            int r0 = wm * 32 + mt * 16 + lr;
            ep[(r0 * NW + wn) * 2 + 0]       = sp[mt][0];
            ep[(r0 * NW + wn) * 2 + 1]       = dp[mt][0];
            ep[((r0 + 8) * NW + wn) * 2 + 0] = sp[mt][1];
            ep[((r0 + 8) * NW + wn) * 2 + 1] = dp[mt][1];
        }
    }
    __syncthreads();
    if (tid < BM && m0 + tid < NN) {
        float s = 0.f, d = 0.f;
        #pragma unroll
        for (int w = 0; w < NW; w++) {
            s += ep[(tid * NW + w) * 2 + 0];
            d += ep[(tid * NW + w) * 2 + 1];
        }
        g_as[m0 + tid] = s;
        g_ad[m0 + tid] = d;
    }
}

// ---------------- warp-per-row single-pass GAT aggregation ----------------
template <int D, bool ADD_BIAS>
__global__ __launch_bounds__(256) void aggregate(
    const float* __restrict__ H, const float* __restrict__ bias,
    float* __restrict__ OUT)
{
    constexpr int V = D / 32;
    int row = blockIdx.x * 8 + (threadIdx.x >> 5);
    if (row >= NN) return;
    int lane = threadIdx.x & 31;
    int beg = g_rowptr[row], end = g_rowptr[row + 1];
    float ad_r = g_ad[row];

    float den = 0.f;
    float acc[V];
    #pragma unroll
    for (int v = 0; v < V; v++) acc[v] = 0.f;

    for (int base = beg; base < end; base += 32) {
        int n = min(32, end - base);
        int s = 0; float ex = 0.f;
        if (lane < n) {
            s = __ldg(&g_colsrc[base + lane]);
            float e = __ldg(&g_as[s]) + ad_r;
            e = e > 0.f ? e : 0.2f * e;
            ex = __expf(e);
            den += ex;
        }
        #pragma unroll 4
        for (int j = 0; j < n; j++) {
            int   sj = __shfl_sync(0xffffffffu, s, j);
            float wj = __shfl_sync(0xffffffffu, ex, j);
            const float* hp = H + (size_t)sj * D + lane * V;
            if constexpr (V == 4) {
                float4 h = __ldg((const float4*)hp);
                acc[0] = fmaf(wj, h.x, acc[0]);
                acc[1] = fmaf(wj, h.y, acc[1]);
                acc[2] = fmaf(wj, h.z, acc[2]);
                acc[3] = fmaf(wj, h.w, acc[3]);
            } else {
                float2 h = __ldg((const float2*)hp);
                acc[0] = fmaf(wj, h.x, acc[0]);
                acc[1] = fmaf(wj, h.y, acc[1]);
            }
        }
    }

    #pragma unroll
    for (int o = 16; o; o >>= 1) den += __shfl_xor_sync(0xffffffffu, den, o);
    float inv = 1.f / (den + 1e-16f);

    float* op = OUT + (size_t)row * D + lane * V;
    if constexpr (ADD_BIAS) {
        #pragma unroll
        for (int v = 0; v < V; v++) acc[v] = fmaf(acc[v], inv, bias[lane * V + v]);
    } else {
        #pragma unroll
        for (int v = 0; v < V; v++) acc[v] *= inv;
    }
    if constexpr (V == 4)
        *(float4*)op = make_float4(acc[0], acc[1], acc[2], acc[3]);
    else
        *(float2*)op = make_float2(acc[0], acc[1]);
}

// ---------------- launch ----------------
extern "C" void kernel_launch(void* const* d_in, const int* in_sizes, int n_in,
                              void* d_out, int out_size) {
    const float* x   = (const float*)d_in[0];
    const void*  ei  = d_in[1];
    const float* W1  = (const float*)d_in[2];
    const float* as1 = (const float*)d_in[3];
    const float* ad1 = (const float*)d_in[4];
    const float* b1  = (const float*)d_in[5];
    const float* W2  = (const float*)d_in[6];
    const float* as2 = (const float*)d_in[7];
    const float* ad2 = (const float*)d_in[8];
    const float* b2  = (const float*)d_in[9];
    float* out = (float*)d_out;

    float *p_h1, *p_out1, *p_h2;
    int   *p_deg;
    cudaGetSymbolAddress((void**)&p_h1,   g_h1);
    cudaGetSymbolAddress((void**)&p_out1, g_out1);
    cudaGetSymbolAddress((void**)&p_h2,   g_h2);
    cudaGetSymbolAddress((void**)&p_deg,  g_deg);

    const int SMEM1 = (64 * 68 + 128 * 68) * 4;   // 52,224 B
    const int SMEM2 = (64 * 68 +  64 * 68) * 4;   // 34,816 B
    cudaFuncSetAttribute(gemm_tc<128, false>,
                         cudaFuncAttributeMaxDynamicSharedMemorySize, SMEM1);
    cudaFuncSetAttribute(gemm_tc<64, true>,
                         cudaFuncAttributeMaxDynamicSharedMemorySize, SMEM2);

    const int nblk = (NN + 1023) / 1024;   // 98
    const int gblocks = (NN + 63) / 64;    // 1563

    // gemm1 stays at kernel-launch slot 4 (ncu's capture point).
    detect_edge_dtype<<<1, 32>>>((const int*)ei);                 // 1
    cudaMemsetAsync(p_deg, 0, NN * sizeof(int));
    histo_edges<<<(EE + 255) / 256, 256>>>(ei);                   // 2
    scan1<<<nblk, 1024>>>();                                      // 3
    gemm_tc<128, false><<<gblocks, 256, SMEM1>>>(x, W1, nullptr, as1, ad1, p_h1); // 4 <- profiled
    scan2<<<1, 128>>>(nblk);                                      // 5
    scan3<<<(NN + 256) / 256, 256>>>();                           // 6
    fill_csr<<<(EE + 255) / 256, 256>>>(ei);                      // 7
    aggregate<128, false><<<(NN + 7) / 8, 256>>>(p_h1, nullptr, p_out1);          // 8
    gemm_tc<64, true><<<gblocks, 128, SMEM2>>>(p_out1, W2, b1, as2, ad2, p_h2);   // 9
    aggregate<64, true><<<(NN + 7) / 8, 256>>>(p_h2, b2, out);                    // 10
}

// round 10
// speedup vs baseline: 1.1398x; 1.1398x over previous
#include <cuda_runtime.h>
#include <cstdint>

#define NN 100000
#define EE 1600000

// ---------------- scratch (no allocations allowed) ----------------
__device__ float g_h1[(size_t)NN * 128];
__device__ float g_out1[(size_t)NN * 128];
__device__ float g_h2[(size_t)NN * 64];
__device__ float g_as[NN];
__device__ float g_ad[NN];
__device__ int   g_deg[NN];
__device__ int   g_rowptr[NN + 1];
__device__ int   g_cursor[NN];
__device__ int   g_bsum[128];
__device__ int   g_colsrc[EE];
__device__ int   g_is64;
__device__ uint32_t g_wf1[16 * 16 * 32 * 4];   // W1 fragments (hi/lo tf32)
__device__ uint32_t g_wf2[16 * 8 * 32 * 4];    // W2 fragments

// ---------------- edge dtype sniff ----------------
__global__ void detect_edge_dtype(const int* __restrict__ ei32) {
    if (threadIdx.x == 0 && blockIdx.x == 0) {
        int all_hi_zero = 1;
        for (int i = 0; i < 256; i++)
            if (ei32[2 * i + 1] != 0) { all_hi_zero = 0; break; }
        g_is64 = all_hi_zero;
    }
}

__device__ __forceinline__ int load_edge(const void* ei, int i, int half) {
    int v;
    if (g_is64) v = (int)((const long long*)ei)[(size_t)half * EE + i];
    else        v = ((const int*)ei)[(size_t)half * EE + i];
    return min(max(v, 0), NN - 1);
}

__global__ __launch_bounds__(256) void histo_edges(const void* __restrict__ ei) {
    int i = blockIdx.x * 256 + threadIdx.x;
    if (i >= EE) return;
    atomicAdd(&g_deg[load_edge(ei, i, 1)], 1);
}

// ---------------- exclusive scan ----------------
__global__ __launch_bounds__(1024) void scan1() {
    __shared__ int sh[1024];
    int i = blockIdx.x * 1024 + threadIdx.x;
    int v = (i < NN) ? g_deg[i] : 0;
    sh[threadIdx.x] = v;
    __syncthreads();
    #pragma unroll
    for (int o = 1; o < 1024; o <<= 1) {
        int t = (threadIdx.x >= o) ? sh[threadIdx.x - o] : 0;
        __syncthreads();
        sh[threadIdx.x] += t;
        __syncthreads();
    }
    if (i < NN) g_rowptr[i] = sh[threadIdx.x] - v;
    if (threadIdx.x == 1023) g_bsum[blockIdx.x] = sh[1023];
}

__global__ void scan2(int nblk) {
    __shared__ int sh[128];
    int v = (threadIdx.x < nblk) ? g_bsum[threadIdx.x] : 0;
    sh[threadIdx.x] = v;
    __syncthreads();
    #pragma unroll
    for (int o = 1; o < 128; o <<= 1) {
        int t = (threadIdx.x >= o) ? sh[threadIdx.x - o] : 0;
        __syncthreads();
        sh[threadIdx.x] += t;
        __syncthreads();
    }
    if (threadIdx.x < nblk) g_bsum[threadIdx.x] = sh[threadIdx.x] - v;
}

__global__ __launch_bounds__(256) void scan3() {
    int i = blockIdx.x * 256 + threadIdx.x;
    if (i < NN) {
        int rp = g_rowptr[i] + g_bsum[i >> 10];
        g_rowptr[i] = rp;
        g_cursor[i] = rp;
    }
    if (i == NN) g_rowptr[NN] = EE;
}

__global__ __launch_bounds__(256) void fill_csr(const void* __restrict__ ei) {
    int e = blockIdx.x * 256 + threadIdx.x;
    if (e >= EE) return;
    int s = load_edge(ei, e, 0);
    int d = load_edge(ei, e, 1);
    int pos = atomicAdd(&g_cursor[d], 1);
    g_colsrc[pos] = s;
}

// ---------------- tf32 helpers ----------------
__device__ __forceinline__ uint32_t f2tf32(float x) {
    uint32_t r;
    asm("cvt.rna.tf32.f32 %0, %1;" : "=r"(r) : "f"(x));
    return r;
}
__device__ __forceinline__ uint32_t tf32lo(float x, uint32_t hi) {
    return f2tf32(x - __uint_as_float(hi));
}

#define MMA_TF32(d, a0, a1, a2, a3, b0, b1)                                \
    asm volatile("mma.sync.aligned.m16n8k8.row.col.f32.tf32.tf32.f32 "     \
        "{%0,%1,%2,%3}, {%4,%5,%6,%7}, {%8,%9}, {%0,%1,%2,%3};"            \
        : "+f"(d[0]), "+f"(d[1]), "+f"(d[2]), "+f"(d[3])                   \
        : "r"(a0), "r"(a1), "r"(a2), "r"(a3), "r"(b0), "r"(b1))

// ---------------- W fragment prep (once per layer) ----------------
// wf[((k8*N8 + n8)*32 + lane)] = {bh0, bh1, bl0, bl1} where
// b0 = W[k8*8 + kq][n8*8 + lr], b1 = W[k8*8 + kq + 4][n8*8 + lr]
// (lane = lr*4 + kq) -- exact fragment the validated mainloop consumed.
__global__ __launch_bounds__(256) void prep_w(const float* __restrict__ W,
                                              uint32_t* __restrict__ wf,
                                              int N8) {
    int t = blockIdx.x * 256 + threadIdx.x;
    if (t >= 16 * N8 * 32) return;
    int lane = t & 31;
    int n8 = (t >> 5) % N8;
    int k8 = (t >> 5) / N8;
    int lr = lane >> 2, kq = lane & 3;
    int N = N8 * 8;
    float w0 = W[(size_t)(k8 * 8 + kq)     * N + n8 * 8 + lr];
    float w1 = W[(size_t)(k8 * 8 + kq + 4) * N + n8 * 8 + lr];
    uint32_t h0 = f2tf32(w0), h1 = f2tf32(w1);
    uint4 v = make_uint4(h0, h1, tf32lo(w0, h0), tf32lo(w1, h1));
    ((uint4*)wf)[t] = v;
}

// ---------------- tensor-core GEMM (3xTF32, zero mainloop cvt) ----------
// A pre-split hi/lo into smem planes at stage time; B fragments pre-split
// in global (prep_w), one LDG.128 per (k8, nt). Fragment mapping identical
// to the R6/R8-validated kernel (rel_err 1.786e-6).
template <int BN, bool RELU_BIAS>
__global__ __launch_bounds__(BN * 2) void gemm_tc(
    const float* __restrict__ X, const uint32_t* __restrict__ WF,
    const float* __restrict__ bin,
    const float* __restrict__ avs, const float* __restrict__ avd,
    float* __restrict__ H)
{
    constexpr int K = 128, BM = 64, KP = 132;   // padded k stride (bank-staggered)
    constexpr int NW = BN / 32;                  // 4 or 2
    constexpr int N8 = BN / 8;                   // 16 or 8
    constexpr int THREADS = BN * 2;

    extern __shared__ float sm[];
    float* AsH = sm;                 // [BM][KP]
    float* AsL = sm + BM * KP;       // [BM][KP]

    const int tid = threadIdx.x, lane = tid & 31, wid = tid >> 5;
    const int wm = wid & 1, wn = wid >> 1;
    const int m0 = blockIdx.x * BM;
    const int lr = lane >> 2, kq = lane & 3;

    // ---- stage A: load, (bias+relu), split hi/lo, natural layout ----
    #pragma unroll
    for (int it = tid; it < BM * (K / 4); it += THREADS) {
        int r = it >> 5, c4 = it & 31;
        float4 v = make_float4(0.f, 0.f, 0.f, 0.f);
        if (m0 + r < NN) {
            v = ((const float4*)X)[(size_t)(m0 + r) * (K / 4) + c4];
            if constexpr (RELU_BIAS) {
                float4 bb = ((const float4*)bin)[c4];
                v.x = fmaxf(v.x + bb.x, 0.f);
                v.y = fmaxf(v.y + bb.y, 0.f);
                v.z = fmaxf(v.z + bb.z, 0.f);
                v.w = fmaxf(v.w + bb.w, 0.f);
            }
        }
        uint32_t hx = f2tf32(v.x), hy = f2tf32(v.y);
        uint32_t hz = f2tf32(v.z), hw = f2tf32(v.w);
        *(uint4*)&AsH[r * KP + c4 * 4] = make_uint4(hx, hy, hz, hw);
        *(uint4*)&AsL[r * KP + c4 * 4] =
            make_uint4(tf32lo(v.x, hx), tf32lo(v.y, hy),
                       tf32lo(v.z, hz), tf32lo(v.w, hw));
    }
    __syncthreads();

    float acc[2][4][4];
    #pragma unroll
    for (int mt = 0; mt < 2; mt++)
        #pragma unroll
        for (int nt = 0; nt < 4; nt++)
            #pragma unroll
            for (int c = 0; c < 4; c++) acc[mt][nt][c] = 0.f;

    const uint4* wf = (const uint4*)WF;

    // ---- mainloop: pure LDS.32 (A) + LDG.128 (B) + MMA ----
    #pragma unroll 4
    for (int k8 = 0; k8 < 16; k8++) {
        int k0 = k8 * 8;
        // B fragments: 4 n-tiles per warp (both BN configs)
        uint4 bw[4];
        #pragma unroll
        for (int nt = 0; nt < 4; nt++)
            bw[nt] = wf[(size_t)(k8 * N8 + wn * 4 + nt) * 32 + lane];

        uint32_t ah[2][4], al[2][4];
        #pragma unroll
        for (int mt = 0; mt < 2; mt++) {
            int base = (wm * 32 + mt * 16 + lr) * KP + k0 + kq;
            ah[mt][0] = *(const uint32_t*)&AsH[base];
            ah[mt][1] = *(const uint32_t*)&AsH[base + 8 * KP];
            ah[mt][2] = *(const uint32_t*)&AsH[base + 4];
            ah[mt][3] = *(const uint32_t*)&AsH[base + 8 * KP + 4];
            al[mt][0] = *(const uint32_t*)&AsL[base];
            al[mt][1] = *(const uint32_t*)&AsL[base + 8 * KP];
            al[mt][2] = *(const uint32_t*)&AsL[base + 4];
            al[mt][3] = *(const uint32_t*)&AsL[base + 8 * KP + 4];
        }
        #pragma unroll
        for (int nt = 0; nt < 4; nt++) {
            #pragma unroll
            for (int mt = 0; mt < 2; mt++) {
                MMA_TF32(acc[mt][nt], ah[mt][0], ah[mt][1], ah[mt][2], ah[mt][3], bw[nt].x, bw[nt].y);
                MMA_TF32(acc[mt][nt], al[mt][0], al[mt][1], al[mt][2], al[mt][3], bw[nt].x, bw[nt].y);
                MMA_TF32(acc[mt][nt], ah[mt][0], ah[mt][1], ah[mt][2], ah[mt][3], bw[nt].z, bw[nt].w);
            }
        }
    }

    // ---- epilogue: H stores + a_src/a_dst logit dots ----
    float sp[2][2], dp[2][2];
    #pragma unroll
    for (int mt = 0; mt < 2; mt++)
        sp[mt][0] = sp[mt][1] = dp[mt][0] = dp[mt][1] = 0.f;

    #pragma unroll
    for (int mt = 0; mt < 2; mt++) {
        int rA = m0 + wm * 32 + mt * 16 + lr;
        int rB = rA + 8;
        #pragma unroll
        for (int nt = 0; nt < 4; nt++) {
            int c = wn * 32 + nt * 8 + kq * 2;
            float s0 = __ldg(&avs[c]), s1 = __ldg(&avs[c + 1]);
            float d0 = __ldg(&avd[c]), d1 = __ldg(&avd[c + 1]);
            sp[mt][0] += acc[mt][nt][0] * s0 + acc[mt][nt][1] * s1;
            dp[mt][0] += acc[mt][nt][0] * d0 + acc[mt][nt][1] * d1;
            sp[mt][1] += acc[mt][nt][2] * s0 + acc[mt][nt][3] * s1;
            dp[mt][1] += acc[mt][nt][2] * d0 + acc[mt][nt][3] * d1;
            if (rA < NN)
                *(float2*)&H[(size_t)rA * BN + c] = make_float2(acc[mt][nt][0], acc[mt][nt][1]);
            if (rB < NN)
                *(float2*)&H[(size_t)rB * BN + c] = make_float2(acc[mt][nt][2], acc[mt][nt][3]);
        }
    }
    #pragma unroll
    for (int o = 1; o <= 2; o <<= 1)
        #pragma unroll
        for (int mt = 0; mt < 2; mt++) {
            sp[mt][0] += __shfl_xor_sync(0xffffffffu, sp[mt][0], o);
            dp[mt][0] += __shfl_xor_sync(0xffffffffu, dp[mt][0], o);
            sp[mt][1] += __shfl_xor_sync(0xffffffffu, sp[mt][1], o);
            dp[mt][1] += __shfl_xor_sync(0xffffffffu, dp[mt][1], o);
        }

    __syncthreads();                 // smem reuse: ep[BM][NW][2]
    float* ep = sm;
    if (kq == 0) {
        #pragma unroll
        for (int mt = 0; mt < 2; mt++) {
            int r0 = wm * 32 + mt * 16 + lr;
            ep[(r0 * NW + wn) * 2 + 0]       = sp[mt][0];
            ep[(r0 * NW + wn) * 2 + 1]       = dp[mt][0];
            ep[((r0 + 8) * NW + wn) * 2 + 0] = sp[mt][1];
            ep[((r0 + 8) * NW + wn) * 2 + 1] = dp[mt][1];
        }
    }
    __syncthreads();
    if (tid < BM && m0 + tid < NN) {
        float s = 0.f, d = 0.f;
        #pragma unroll
        for (int w = 0; w < NW; w++) {
            s += ep[(tid * NW + w) * 2 + 0];
            d += ep[(tid * NW + w) * 2 + 1];
        }
        g_as[m0 + tid] = s;
        g_ad[m0 + tid] = d;
    }
}

// ---------------- warp-per-row single-pass GAT aggregation ----------------
template <int D, bool ADD_BIAS>
__global__ __launch_bounds__(256) void aggregate(
    const float* __restrict__ H, const float* __restrict__ bias,
    float* __restrict__ OUT)
{
    constexpr int V = D / 32;
    int row = blockIdx.x * 8 + (threadIdx.x >> 5);
    if (row >= NN) return;
    int lane = threadIdx.x & 31;
    int beg = g_rowptr[row], end = g_rowptr[row + 1];
    float ad_r = g_ad[row];

    float den = 0.f;
    float acc[V];
    #pragma unroll
    for (int v = 0; v < V; v++) acc[v] = 0.f;

    for (int base = beg; base < end; base += 32) {
        int n = min(32, end - base);
        int s = 0; float ex = 0.f;
        if (lane < n) {
            s = __ldg(&g_colsrc[base + lane]);
            float e = __ldg(&g_as[s]) + ad_r;
            e = e > 0.f ? e : 0.2f * e;
            ex = __expf(e);
            den += ex;
        }
        #pragma unroll 4
        for (int j = 0; j < n; j++) {
            int   sj = __shfl_sync(0xffffffffu, s, j);
            float wj = __shfl_sync(0xffffffffu, ex, j);
            const float* hp = H + (size_t)sj * D + lane * V;
            if constexpr (V == 4) {
                float4 h = __ldg((const float4*)hp);
                acc[0] = fmaf(wj, h.x, acc[0]);
                acc[1] = fmaf(wj, h.y, acc[1]);
                acc[2] = fmaf(wj, h.z, acc[2]);
                acc[3] = fmaf(wj, h.w, acc[3]);
            } else {
                float2 h = __ldg((const float2*)hp);
                acc[0] = fmaf(wj, h.x, acc[0]);
                acc[1] = fmaf(wj, h.y, acc[1]);
            }
        }
    }

    #pragma unroll
    for (int o = 16; o; o >>= 1) den += __shfl_xor_sync(0xffffffffu, den, o);
    float inv = 1.f / (den + 1e-16f);

    float* op = OUT + (size_t)row * D + lane * V;
    if constexpr (ADD_BIAS) {
        #pragma unroll
        for (int v = 0; v < V; v++) acc[v] = fmaf(acc[v], inv, bias[lane * V + v]);
    } else {
        #pragma unroll
        for (int v = 0; v < V; v++) acc[v] *= inv;
    }
    if constexpr (V == 4)
        *(float4*)op = make_float4(acc[0], acc[1], acc[2], acc[3]);
    else
        *(float2*)op = make_float2(acc[0], acc[1]);
}

// ---------------- launch ----------------
extern "C" void kernel_launch(void* const* d_in, const int* in_sizes, int n_in,
                              void* d_out, int out_size) {
    const float* x   = (const float*)d_in[0];
    const void*  ei  = d_in[1];
    const float* W1  = (const float*)d_in[2];
    const float* as1 = (const float*)d_in[3];
    const float* ad1 = (const float*)d_in[4];
    const float* b1  = (const float*)d_in[5];
    const float* W2  = (const float*)d_in[6];
    const float* as2 = (const float*)d_in[7];
    const float* ad2 = (const float*)d_in[8];
    const float* b2  = (const float*)d_in[9];
    float* out = (float*)d_out;

    float *p_h1, *p_out1, *p_h2;
    int   *p_deg;
    uint32_t *p_wf1, *p_wf2;
    cudaGetSymbolAddress((void**)&p_h1,   g_h1);
    cudaGetSymbolAddress((void**)&p_out1, g_out1);
    cudaGetSymbolAddress((void**)&p_h2,   g_h2);
    cudaGetSymbolAddress((void**)&p_deg,  g_deg);
    cudaGetSymbolAddress((void**)&p_wf1,  g_wf1);
    cudaGetSymbolAddress((void**)&p_wf2,  g_wf2);

    const int SMEM = 2 * 64 * 132 * 4;   // 67,584 B (both layers)
    cudaFuncSetAttribute(gemm_tc<128, false>,
                         cudaFuncAttributeMaxDynamicSharedMemorySize, SMEM);
    cudaFuncSetAttribute(gemm_tc<64, true>,
                         cudaFuncAttributeMaxDynamicSharedMemorySize, SMEM);

    const int nblk = (NN + 1023) / 1024;   // 98
    const int gblocks = (NN + 63) / 64;    // 1563

    // gemm1 stays at kernel-launch slot 4 (ncu's capture point).
    detect_edge_dtype<<<1, 32>>>((const int*)ei);                          // 1
    cudaMemsetAsync(p_deg, 0, NN * sizeof(int));
    prep_w<<<(16 * 16 * 32 + 255) / 256, 256>>>(W1, p_wf1, 16);            // 2
    histo_edges<<<(EE + 255) / 256, 256>>>(ei);                            // 3
    gemm_tc<128, false><<<gblocks, 256, SMEM>>>(x, p_wf1, nullptr, as1, ad1, p_h1); // 4 <- profiled
    scan1<<<nblk, 1024>>>();                                               // 5
    scan2<<<1, 128>>>(nblk);                                               // 6
    scan3<<<(NN + 256) / 256, 256>>>();                                    // 7
    fill_csr<<<(EE + 255) / 256, 256>>>(ei);                               // 8
    aggregate<128, false><<<(NN + 7) / 8, 256>>>(p_h1, nullptr, p_out1);   // 9
    prep_w<<<(16 * 8 * 32 + 255) / 256, 256>>>(W2, p_wf2, 8);              // 10
    gemm_tc<64, true><<<gblocks, 128, SMEM>>>(p_out1, p_wf2, b1, as2, ad2, p_h2);   // 11
    aggregate<64, true><<<(NN + 7) / 8, 256>>>(p_h2, b2, out);             // 12
}

// round 11
// speedup vs baseline: 1.2227x; 1.0727x over previous
#include <cuda_runtime.h>
#include <cstdint>

#define NN 100000
#define EE 1600000

// ---------------- scratch (no allocations allowed) ----------------
__device__ float g_h1[(size_t)NN * 128];
__device__ float g_out1[(size_t)NN * 128];
__device__ float g_h2[(size_t)NN * 64];
__device__ float g_as[NN];
__device__ float g_ad[NN];
__device__ int   g_deg[NN];
__device__ int   g_rowptr[NN + 1];
__device__ int   g_cursor[NN];
__device__ int   g_bsum[128];
__device__ int   g_colsrc[EE];
__device__ int   g_is64;
__device__ uint32_t g_wf1[16 * 16 * 32 * 4];   // W1 fragments (hi/lo tf32)
__device__ uint32_t g_wf2[16 * 8 * 32 * 4];    // W2 fragments

// ---------------- edge dtype sniff ----------------
__global__ void detect_edge_dtype(const int* __restrict__ ei32) {
    if (threadIdx.x == 0 && blockIdx.x == 0) {
        int all_hi_zero = 1;
        for (int i = 0; i < 256; i++)
            if (ei32[2 * i + 1] != 0) { all_hi_zero = 0; break; }
        g_is64 = all_hi_zero;
    }
}

__device__ __forceinline__ int load_edge(const void* ei, int i, int half) {
    int v;
    if (g_is64) v = (int)((const long long*)ei)[(size_t)half * EE + i];
    else        v = ((const int*)ei)[(size_t)half * EE + i];
    return min(max(v, 0), NN - 1);
}

__global__ __launch_bounds__(256) void histo_edges(const void* __restrict__ ei) {
    int i = blockIdx.x * 256 + threadIdx.x;
    if (i >= EE) return;
    atomicAdd(&g_deg[load_edge(ei, i, 1)], 1);
}

// ---------------- exclusive scan ----------------
__global__ __launch_bounds__(1024) void scan1() {
    __shared__ int sh[1024];
    int i = blockIdx.x * 1024 + threadIdx.x;
    int v = (i < NN) ? g_deg[i] : 0;
    sh[threadIdx.x] = v;
    __syncthreads();
    #pragma unroll
    for (int o = 1; o < 1024; o <<= 1) {
        int t = (threadIdx.x >= o) ? sh[threadIdx.x - o] : 0;
        __syncthreads();
        sh[threadIdx.x] += t;
        __syncthreads();
    }
    if (i < NN) g_rowptr[i] = sh[threadIdx.x] - v;
    if (threadIdx.x == 1023) g_bsum[blockIdx.x] = sh[1023];
}

__global__ void scan2(int nblk) {
    __shared__ int sh[128];
    int v = (threadIdx.x < nblk) ? g_bsum[threadIdx.x] : 0;
    sh[threadIdx.x] = v;
    __syncthreads();
    #pragma unroll
    for (int o = 1; o < 128; o <<= 1) {
        int t = (threadIdx.x >= o) ? sh[threadIdx.x - o] : 0;
        __syncthreads();
        sh[threadIdx.x] += t;
        __syncthreads();
    }
    if (threadIdx.x < nblk) g_bsum[threadIdx.x] = sh[threadIdx.x] - v;
}

__global__ __launch_bounds__(256) void scan3() {
    int i = blockIdx.x * 256 + threadIdx.x;
    if (i < NN) {
        int rp = g_rowptr[i] + g_bsum[i >> 10];
        g_rowptr[i] = rp;
        g_cursor[i] = rp;
    }
    if (i == NN) g_rowptr[NN] = EE;
}

__global__ __launch_bounds__(256) void fill_csr(const void* __restrict__ ei) {
    int e = blockIdx.x * 256 + threadIdx.x;
    if (e >= EE) return;
    int s = load_edge(ei, e, 0);
    int d = load_edge(ei, e, 1);
    int pos = atomicAdd(&g_cursor[d], 1);
    g_colsrc[pos] = s;
}

// ---------------- tf32 helpers ----------------
__device__ __forceinline__ uint32_t f2tf32(float x) {
    uint32_t r;
    asm("cvt.rna.tf32.f32 %0, %1;" : "=r"(r) : "f"(x));
    return r;
}
__device__ __forceinline__ uint32_t tf32lo(float x, uint32_t hi) {
    return f2tf32(x - __uint_as_float(hi));
}

#define MMA_TF32(d, a0, a1, a2, a3, b0, b1)                                \
    asm volatile("mma.sync.aligned.m16n8k8.row.col.f32.tf32.tf32.f32 "     \
        "{%0,%1,%2,%3}, {%4,%5,%6,%7}, {%8,%9}, {%0,%1,%2,%3};"            \
        : "+f"(d[0]), "+f"(d[1]), "+f"(d[2]), "+f"(d[3])                   \
        : "r"(a0), "r"(a1), "r"(a2), "r"(a3), "r"(b0), "r"(b1))

// ---------------- W fragment prep (once per layer) ----------------
__global__ __launch_bounds__(256) void prep_w(const float* __restrict__ W,
                                              uint32_t* __restrict__ wf,
                                              int N8) {
    int t = blockIdx.x * 256 + threadIdx.x;
    if (t >= 16 * N8 * 32) return;
    int lane = t & 31;
    int n8 = (t >> 5) % N8;
    int k8 = (t >> 5) / N8;
    int lr = lane >> 2, kq = lane & 3;
    int N = N8 * 8;
    float w0 = W[(size_t)(k8 * 8 + kq)     * N + n8 * 8 + lr];
    float w1 = W[(size_t)(k8 * 8 + kq + 4) * N + n8 * 8 + lr];
    uint32_t h0 = f2tf32(w0), h1 = f2tf32(w1);
    uint4 v = make_uint4(h0, h1, tf32lo(w0, h0), tf32lo(w1, h1));
    ((uint4*)wf)[t] = v;
}

// ---------------- tensor-core GEMM (3xTF32) ----------------------------
// 256 threads both layers: 8 warps = 2 m-slabs x 4 n-groups, NTW=BN/32
// n-tiles per warp. MMA split passes interleaved across tiles so no
// back-to-back RAW on any accumulator (dep distance 2*NTW).
// Per-acc MMA order (hi*hi, lo*hi, hi*lo) unchanged -> bitwise-identical
// numerics to the validated path (rel_err 1.786e-6).
template <int BN, bool RELU_BIAS>
__global__ __launch_bounds__(256) void gemm_tc(
    const float* __restrict__ X, const uint32_t* __restrict__ WF,
    const float* __restrict__ bin,
    const float* __restrict__ avs, const float* __restrict__ avd,
    float* __restrict__ H)
{
    constexpr int K = 128, BM = 64, KP = 132;
    constexpr int N8 = BN / 8;       // 16 or 8
    constexpr int NTW = BN / 32;     // n-tiles per warp: 4 or 2
    constexpr int THREADS = 256;

    extern __shared__ float sm[];
    float* AsH = sm;                 // [BM][KP]
    float* AsL = sm + BM * KP;       // [BM][KP]

    const int tid = threadIdx.x, lane = tid & 31, wid = tid >> 5;
    const int wm = wid & 1, wn = wid >> 1;       // wn in 0..3
    const int m0 = blockIdx.x * BM;
    const int lr = lane >> 2, kq = lane & 3;

    // ---- stage A: load, (bias+relu), split hi/lo, natural layout ----
    #pragma unroll
    for (int it = tid; it < BM * (K / 4); it += THREADS) {
        int r = it >> 5, c4 = it & 31;
        float4 v = make_float4(0.f, 0.f, 0.f, 0.f);
        if (m0 + r < NN) {
            v = ((const float4*)X)[(size_t)(m0 + r) * (K / 4) + c4];
            if constexpr (RELU_BIAS) {
                float4 bb = ((const float4*)bin)[c4];
                v.x = fmaxf(v.x + bb.x, 0.f);
                v.y = fmaxf(v.y + bb.y, 0.f);
                v.z = fmaxf(v.z + bb.z, 0.f);
                v.w = fmaxf(v.w + bb.w, 0.f);
            }
        }
        uint32_t hx = f2tf32(v.x), hy = f2tf32(v.y);
        uint32_t hz = f2tf32(v.z), hw = f2tf32(v.w);
        *(uint4*)&AsH[r * KP + c4 * 4] = make_uint4(hx, hy, hz, hw);
        *(uint4*)&AsL[r * KP + c4 * 4] =
            make_uint4(tf32lo(v.x, hx), tf32lo(v.y, hy),
                       tf32lo(v.z, hz), tf32lo(v.w, hw));
    }
    __syncthreads();

    float acc[2][NTW][4];
    #pragma unroll
    for (int mt = 0; mt < 2; mt++)
        #pragma unroll
        for (int nt = 0; nt < NTW; nt++)
            #pragma unroll
            for (int c = 0; c < 4; c++) acc[mt][nt][c] = 0.f;

    const uint4* wf = (const uint4*)WF;

    // ---- mainloop: LDS.32 (A) + LDG.128 (B) + interleaved MMA passes ----
    #pragma unroll 4
    for (int k8 = 0; k8 < 16; k8++) {
        int k0 = k8 * 8;
        uint4 bw[NTW];
        #pragma unroll
        for (int nt = 0; nt < NTW; nt++)
            bw[nt] = wf[(size_t)(k8 * N8 + wn * NTW + nt) * 32 + lane];

        uint32_t ah[2][4], al[2][4];
        #pragma unroll
        for (int mt = 0; mt < 2; mt++) {
            int base = (wm * 32 + mt * 16 + lr) * KP + k0 + kq;
            ah[mt][0] = *(const uint32_t*)&AsH[base];
            ah[mt][1] = *(const uint32_t*)&AsH[base + 8 * KP];
            ah[mt][2] = *(const uint32_t*)&AsH[base + 4];
            ah[mt][3] = *(const uint32_t*)&AsH[base + 8 * KP + 4];
            al[mt][0] = *(const uint32_t*)&AsL[base];
            al[mt][1] = *(const uint32_t*)&AsL[base + 8 * KP];
            al[mt][2] = *(const uint32_t*)&AsL[base + 4];
            al[mt][3] = *(const uint32_t*)&AsL[base + 8 * KP + 4];
        }
        // pass 1: hi*hi across all tiles
        #pragma unroll
        for (int nt = 0; nt < NTW; nt++)
            #pragma unroll
            for (int mt = 0; mt < 2; mt++)
                MMA_TF32(acc[mt][nt], ah[mt][0], ah[mt][1], ah[mt][2], ah[mt][3], bw[nt].x, bw[nt].y);
        // pass 2: lo*hi
        #pragma unroll
        for (int nt = 0; nt < NTW; nt++)
            #pragma unroll
            for (int mt = 0; mt < 2; mt++)
                MMA_TF32(acc[mt][nt], al[mt][0], al[mt][1], al[mt][2], al[mt][3], bw[nt].x, bw[nt].y);
        // pass 3: hi*lo
        #pragma unroll
        for (int nt = 0; nt < NTW; nt++)
            #pragma unroll
            for (int mt = 0; mt < 2; mt++)
                MMA_TF32(acc[mt][nt], ah[mt][0], ah[mt][1], ah[mt][2], ah[mt][3], bw[nt].z, bw[nt].w);
    }

    // ---- epilogue: H stores + a_src/a_dst logit dots ----
    float sp[2][2], dp[2][2];
    #pragma unroll
    for (int mt = 0; mt < 2; mt++)
        sp[mt][0] = sp[mt][1] = dp[mt][0] = dp[mt][1] = 0.f;

    #pragma unroll
    for (int mt = 0; mt < 2; mt++) {
        int rA = m0 + wm * 32 + mt * 16 + lr;
        int rB = rA + 8;
        #pragma unroll
        for (int nt = 0; nt < NTW; nt++) {
            int c = (wn * NTW + nt) * 8 + kq * 2;
            float s0 = __ldg(&avs[c]), s1 = __ldg(&avs[c + 1]);
            float d0 = __ldg(&avd[c]), d1 = __ldg(&avd[c + 1]);
            sp[mt][0] += acc[mt][nt][0] * s0 + acc[mt][nt][1] * s1;
            dp[mt][0] += acc[mt][nt][0] * d0 + acc[mt][nt][1] * d1;
            sp[mt][1] += acc[mt][nt][2] * s0 + acc[mt][nt][3] * s1;
            dp[mt][1] += acc[mt][nt][2] * d0 + acc[mt][nt][3] * d1;
            if (rA < NN)
                *(float2*)&H[(size_t)rA * BN + c] = make_float2(acc[mt][nt][0], acc[mt][nt][1]);
            if (rB < NN)
                *(float2*)&H[(size_t)rB * BN + c] = make_float2(acc[mt][nt][2], acc[mt][nt][3]);
        }
    }
    #pragma unroll
    for (int o = 1; o <= 2; o <<= 1)
        #pragma unroll
        for (int mt = 0; mt < 2; mt++) {
            sp[mt][0] += __shfl_xor_sync(0xffffffffu, sp[mt][0], o);
            dp[mt][0] += __shfl_xor_sync(0xffffffffu, dp[mt][0], o);
            sp[mt][1] += __shfl_xor_sync(0xffffffffu, sp[mt][1], o);
            dp[mt][1] += __shfl_xor_sync(0xffffffffu, dp[mt][1], o);
        }

    __syncthreads();                 // smem reuse: ep[BM][4][2]
    float* ep = sm;
    if (kq == 0) {
        #pragma unroll
        for (int mt = 0; mt < 2; mt++) {
            int r0 = wm * 32 + mt * 16 + lr;
            ep[(r0 * 4 + wn) * 2 + 0]       = sp[mt][0];
            ep[(r0 * 4 + wn) * 2 + 1]       = dp[mt][0];
            ep[((r0 + 8) * 4 + wn) * 2 + 0] = sp[mt][1];
            ep[((r0 + 8) * 4 + wn) * 2 + 1] = dp[mt][1];
        }
    }
    __syncthreads();
    if (tid < BM && m0 + tid < NN) {
        float s = 0.f, d = 0.f;
        #pragma unroll
        for (int w = 0; w < 4; w++) {
            s += ep[(tid * 4 + w) * 2 + 0];
            d += ep[(tid * 4 + w) * 2 + 1];
        }
        g_as[m0 + tid] = s;
        g_ad[m0 + tid] = d;
    }
}

// ---------------- warp-per-row single-pass GAT aggregation ----------------
template <int D, bool ADD_BIAS>
__global__ __launch_bounds__(256) void aggregate(
    const float* __restrict__ H, const float* __restrict__ bias,
    float* __restrict__ OUT)
{
    constexpr int V = D / 32;
    int row = blockIdx.x * 8 + (threadIdx.x >> 5);
    if (row >= NN) return;
    int lane = threadIdx.x & 31;
    int beg = g_rowptr[row], end = g_rowptr[row + 1];
    float ad_r = g_ad[row];

    float den = 0.f;
    float acc[V];
    #pragma unroll
    for (int v = 0; v < V; v++) acc[v] = 0.f;

    for (int base = beg; base < end; base += 32) {
        int n = min(32, end - base);
        int s = 0; float ex = 0.f;
        if (lane < n) {
            s = __ldg(&g_colsrc[base + lane]);
            float e = __ldg(&g_as[s]) + ad_r;
            e = e > 0.f ? e : 0.2f * e;
            ex = __expf(e);
            den += ex;
        }
        #pragma unroll 4
        for (int j = 0; j < n; j++) {
            int   sj = __shfl_sync(0xffffffffu, s, j);
            float wj = __shfl_sync(0xffffffffu, ex, j);
            const float* hp = H + (size_t)sj * D + lane * V;
            if constexpr (V == 4) {
                float4 h = __ldg((const float4*)hp);
                acc[0] = fmaf(wj, h.x, acc[0]);
                acc[1] = fmaf(wj, h.y, acc[1]);
                acc[2] = fmaf(wj, h.z, acc[2]);
                acc[3] = fmaf(wj, h.w, acc[3]);
            } else {
                float2 h = __ldg((const float2*)hp);
                acc[0] = fmaf(wj, h.x, acc[0]);
                acc[1] = fmaf(wj, h.y, acc[1]);
            }
        }
    }

    #pragma unroll
    for (int o = 16; o; o >>= 1) den += __shfl_xor_sync(0xffffffffu, den, o);
    float inv = 1.f / (den + 1e-16f);

    float* op = OUT + (size_t)row * D + lane * V;
    if constexpr (ADD_BIAS) {
        #pragma unroll
        for (int v = 0; v < V; v++) acc[v] = fmaf(acc[v], inv, bias[lane * V + v]);
    } else {
        #pragma unroll
        for (int v = 0; v < V; v++) acc[v] *= inv;
    }
    if constexpr (V == 4)
        *(float4*)op = make_float4(acc[0], acc[1], acc[2], acc[3]);
    else
        *(float2*)op = make_float2(acc[0], acc[1]);
}

// ---------------- launch ----------------
extern "C" void kernel_launch(void* const* d_in, const int* in_sizes, int n_in,
                              void* d_out, int out_size) {
    const float* x   = (const float*)d_in[0];
    const void*  ei  = d_in[1];
    const float* W1  = (const float*)d_in[2];
    const float* as1 = (const float*)d_in[3];
    const float* ad1 = (const float*)d_in[4];
    const float* b1  = (const float*)d_in[5];
    const float* W2  = (const float*)d_in[6];
    const float* as2 = (const float*)d_in[7];
    const float* ad2 = (const float*)d_in[8];
    const float* b2  = (const float*)d_in[9];
    float* out = (float*)d_out;

    float *p_h1, *p_out1, *p_h2;
    int   *p_deg;
    uint32_t *p_wf1, *p_wf2;
    cudaGetSymbolAddress((void**)&p_h1,   g_h1);
    cudaGetSymbolAddress((void**)&p_out1, g_out1);
    cudaGetSymbolAddress((void**)&p_h2,   g_h2);
    cudaGetSymbolAddress((void**)&p_deg,  g_deg);
    cudaGetSymbolAddress((void**)&p_wf1,  g_wf1);
    cudaGetSymbolAddress((void**)&p_wf2,  g_wf2);

    const int SMEM = 2 * 64 * 132 * 4;   // 67,584 B (both layers)
    cudaFuncSetAttribute(gemm_tc<128, false>,
                         cudaFuncAttributeMaxDynamicSharedMemorySize, SMEM);
    cudaFuncSetAttribute(gemm_tc<64, true>,
                         cudaFuncAttributeMaxDynamicSharedMemorySize, SMEM);

    const int nblk = (NN + 1023) / 1024;   // 98
    const int gblocks = (NN + 63) / 64;    // 1563

    // gemm1 stays at kernel-launch slot 4 (ncu's capture point).
    detect_edge_dtype<<<1, 32>>>((const int*)ei);                          // 1
    cudaMemsetAsync(p_deg, 0, NN * sizeof(int));
    prep_w<<<(16 * 16 * 32 + 255) / 256, 256>>>(W1, p_wf1, 16);            // 2
    histo_edges<<<(EE + 255) / 256, 256>>>(ei);                            // 3
    gemm_tc<128, false><<<gblocks, 256, SMEM>>>(x, p_wf1, nullptr, as1, ad1, p_h1); // 4 <- profiled
    scan1<<<nblk, 1024>>>();                                               // 5
    scan2<<<1, 128>>>(nblk);                                               // 6
    scan3<<<(NN + 256) / 256, 256>>>();                                    // 7
    fill_csr<<<(EE + 255) / 256, 256>>>(ei);                               // 8
    aggregate<128, false><<<(NN + 7) / 8, 256>>>(p_h1, nullptr, p_out1);   // 9
    prep_w<<<(16 * 8 * 32 + 255) / 256, 256>>>(W2, p_wf2, 8);              // 10
    gemm_tc<64, true><<<gblocks, 256, SMEM>>>(p_out1, p_wf2, b1, as2, ad2, p_h2);   // 11
    aggregate<64, true><<<(NN + 7) / 8, 256>>>(p_h2, b2, out);             // 12
}

// round 12
// speedup vs baseline: 1.2736x; 1.0416x over previous
#include <cuda_runtime.h>
#include <cstdint>

#define NN 100000
#define EE 1600000

// ---------------- scratch (no allocations allowed) ----------------
__device__ float g_h1[(size_t)NN * 128];
__device__ float g_out1[(size_t)NN * 128];
__device__ float g_h2[(size_t)NN * 64];
__device__ float g_as[NN];
__device__ float g_ad[NN];
__device__ int   g_deg[NN];
__device__ int   g_rowptr[NN + 1];
__device__ int   g_cursor[NN];
__device__ int   g_bsum[128];
__device__ int   g_colsrc[EE];
__device__ int   g_is64;
__device__ uint32_t g_wf1[16 * 16 * 32 * 4];   // W1 fragments (hi/lo tf32)
__device__ uint32_t g_wf2[16 * 8 * 32 * 4];    // W2 fragments

// ---------------- edge dtype sniff ----------------
__global__ void detect_edge_dtype(const int* __restrict__ ei32) {
    if (threadIdx.x == 0 && blockIdx.x == 0) {
        int all_hi_zero = 1;
        for (int i = 0; i < 256; i++)
            if (ei32[2 * i + 1] != 0) { all_hi_zero = 0; break; }
        g_is64 = all_hi_zero;
    }
}

__device__ __forceinline__ int load_edge(const void* ei, int i, int half) {
    int v;
    if (g_is64) v = (int)((const long long*)ei)[(size_t)half * EE + i];
    else        v = ((const int*)ei)[(size_t)half * EE + i];
    return min(max(v, 0), NN - 1);
}

__global__ __launch_bounds__(256) void histo_edges(const void* __restrict__ ei) {
    int i = blockIdx.x * 256 + threadIdx.x;
    if (i >= EE) return;
    atomicAdd(&g_deg[load_edge(ei, i, 1)], 1);
}

// ---------------- exclusive scan ----------------
__global__ __launch_bounds__(1024) void scan1() {
    __shared__ int sh[1024];
    int i = blockIdx.x * 1024 + threadIdx.x;
    int v = (i < NN) ? g_deg[i] : 0;
    sh[threadIdx.x] = v;
    __syncthreads();
    #pragma unroll
    for (int o = 1; o < 1024; o <<= 1) {
        int t = (threadIdx.x >= o) ? sh[threadIdx.x - o] : 0;
        __syncthreads();
        sh[threadIdx.x] += t;
        __syncthreads();
    }
    if (i < NN) g_rowptr[i] = sh[threadIdx.x] - v;
    if (threadIdx.x == 1023) g_bsum[blockIdx.x] = sh[1023];
}

__global__ void scan2(int nblk) {
    __shared__ int sh[128];
    int v = (threadIdx.x < nblk) ? g_bsum[threadIdx.x] : 0;
    sh[threadIdx.x] = v;
    __syncthreads();
    #pragma unroll
    for (int o = 1; o < 128; o <<= 1) {
        int t = (threadIdx.x >= o) ? sh[threadIdx.x - o] : 0;
        __syncthreads();
        sh[threadIdx.x] += t;
        __syncthreads();
    }
    if (threadIdx.x < nblk) g_bsum[threadIdx.x] = sh[threadIdx.x] - v;
}

__global__ __launch_bounds__(256) void scan3() {
    int i = blockIdx.x * 256 + threadIdx.x;
    if (i < NN) {
        int rp = g_rowptr[i] + g_bsum[i >> 10];
        g_rowptr[i] = rp;
        g_cursor[i] = rp;
    }
    if (i == NN) g_rowptr[NN] = EE;
}

__global__ __launch_bounds__(256) void fill_csr(const void* __restrict__ ei) {
    int e = blockIdx.x * 256 + threadIdx.x;
    if (e >= EE) return;
    int s = load_edge(ei, e, 0);
    int d = load_edge(ei, e, 1);
    int pos = atomicAdd(&g_cursor[d], 1);
    g_colsrc[pos] = s;
}

// ---------------- tf32 helpers ----------------
__device__ __forceinline__ uint32_t f2tf32(float x) {
    uint32_t r;
    asm("cvt.rna.tf32.f32 %0, %1;" : "=r"(r) : "f"(x));
    return r;
}
__device__ __forceinline__ uint32_t tf32lo(float x, uint32_t hi) {
    return f2tf32(x - __uint_as_float(hi));
}

#define MMA_TF32(d, a0, a1, a2, a3, b0, b1)                                \
    asm volatile("mma.sync.aligned.m16n8k8.row.col.f32.tf32.tf32.f32 "     \
        "{%0,%1,%2,%3}, {%4,%5,%6,%7}, {%8,%9}, {%0,%1,%2,%3};"            \
        : "+f"(d[0]), "+f"(d[1]), "+f"(d[2]), "+f"(d[3])                   \
        : "r"(a0), "r"(a1), "r"(a2), "r"(a3), "r"(b0), "r"(b1))

// ---------------- W fragment prep (once per layer) ----------------
__global__ __launch_bounds__(256) void prep_w(const float* __restrict__ W,
                                              uint32_t* __restrict__ wf,
                                              int N8) {
    int t = blockIdx.x * 256 + threadIdx.x;
    if (t >= 16 * N8 * 32) return;
    int lane = t & 31;
    int n8 = (t >> 5) % N8;
    int k8 = (t >> 5) / N8;
    int lr = lane >> 2, kq = lane & 3;
    int N = N8 * 8;
    float w0 = W[(size_t)(k8 * 8 + kq)     * N + n8 * 8 + lr];
    float w1 = W[(size_t)(k8 * 8 + kq + 4) * N + n8 * 8 + lr];
    uint32_t h0 = f2tf32(w0), h1 = f2tf32(w1);
    uint4 v = make_uint4(h0, h1, tf32lo(w0, h0), tf32lo(w1, h1));
    ((uint4*)wf)[t] = v;
}

// ---------------- tensor-core GEMM (3xTF32) ----------------------------
// 256 threads: 8 warps = 2 m-slabs x 4 n-groups, NTW=BN/32 n-tiles/warp.
// MMA split passes interleaved across tiles (no back-to-back RAW).
// Per-acc MMA order (hi*hi, lo*hi, hi*lo) -> bitwise-identical numerics
// to the validated path (rel_err 1.786e-6).
template <int BN, bool RELU_BIAS>
__global__ __launch_bounds__(256) void gemm_tc(
    const float* __restrict__ X, const uint32_t* __restrict__ WF,
    const float* __restrict__ bin,
    const float* __restrict__ avs, const float* __restrict__ avd,
    float* __restrict__ H)
{
    constexpr int K = 128, BM = 64, KP = 132;
    constexpr int N8 = BN / 8;       // 16 or 8
    constexpr int NTW = BN / 32;     // n-tiles per warp: 4 or 2
    constexpr int THREADS = 256;

    extern __shared__ float sm[];
    float* AsH = sm;                 // [BM][KP]
    float* AsL = sm + BM * KP;       // [BM][KP]

    const int tid = threadIdx.x, lane = tid & 31, wid = tid >> 5;
    const int wm = wid & 1, wn = wid >> 1;       // wn in 0..3
    const int m0 = blockIdx.x * BM;
    const int lr = lane >> 2, kq = lane & 3;

    // ---- stage A: load, (bias+relu), split hi/lo, natural layout ----
    #pragma unroll
    for (int it = tid; it < BM * (K / 4); it += THREADS) {
        int r = it >> 5, c4 = it & 31;
        float4 v = make_float4(0.f, 0.f, 0.f, 0.f);
        if (m0 + r < NN) {
            v = ((const float4*)X)[(size_t)(m0 + r) * (K / 4) + c4];
            if constexpr (RELU_BIAS) {
                float4 bb = ((const float4*)bin)[c4];
                v.x = fmaxf(v.x + bb.x, 0.f);
                v.y = fmaxf(v.y + bb.y, 0.f);
                v.z = fmaxf(v.z + bb.z, 0.f);
                v.w = fmaxf(v.w + bb.w, 0.f);
            }
        }
        uint32_t hx = f2tf32(v.x), hy = f2tf32(v.y);
        uint32_t hz = f2tf32(v.z), hw = f2tf32(v.w);
        *(uint4*)&AsH[r * KP + c4 * 4] = make_uint4(hx, hy, hz, hw);
        *(uint4*)&AsL[r * KP + c4 * 4] =
            make_uint4(tf32lo(v.x, hx), tf32lo(v.y, hy),
                       tf32lo(v.z, hz), tf32lo(v.w, hw));
    }
    __syncthreads();

    float acc[2][NTW][4];
    #pragma unroll
    for (int mt = 0; mt < 2; mt++)
        #pragma unroll
        for (int nt = 0; nt < NTW; nt++)
            #pragma unroll
            for (int c = 0; c < 4; c++) acc[mt][nt][c] = 0.f;

    const uint4* wf = (const uint4*)WF;

    // ---- mainloop: LDS.32 (A) + LDG.128 (B) + interleaved MMA passes ----
    #pragma unroll 4
    for (int k8 = 0; k8 < 16; k8++) {
        int k0 = k8 * 8;
        uint4 bw[NTW];
        #pragma unroll
        for (int nt = 0; nt < NTW; nt++)
            bw[nt] = wf[(size_t)(k8 * N8 + wn * NTW + nt) * 32 + lane];

        uint32_t ah[2][4], al[2][4];
        #pragma unroll
        for (int mt = 0; mt < 2; mt++) {
            int base = (wm * 32 + mt * 16 + lr) * KP + k0 + kq;
            ah[mt][0] = *(const uint32_t*)&AsH[base];
            ah[mt][1] = *(const uint32_t*)&AsH[base + 8 * KP];
            ah[mt][2] = *(const uint32_t*)&AsH[base + 4];
            ah[mt][3] = *(const uint32_t*)&AsH[base + 8 * KP + 4];
            al[mt][0] = *(const uint32_t*)&AsL[base];
            al[mt][1] = *(const uint32_t*)&AsL[base + 8 * KP];
            al[mt][2] = *(const uint32_t*)&AsL[base + 4];
            al[mt][3] = *(const uint32_t*)&AsL[base + 8 * KP + 4];
        }
        // pass 1: hi*hi across all tiles
        #pragma unroll
        for (int nt = 0; nt < NTW; nt++)
            #pragma unroll
            for (int mt = 0; mt < 2; mt++)
                MMA_TF32(acc[mt][nt], ah[mt][0], ah[mt][1], ah[mt][2], ah[mt][3], bw[nt].x, bw[nt].y);
        // pass 2: lo*hi
        #pragma unroll
        for (int nt = 0; nt < NTW; nt++)
            #pragma unroll
            for (int mt = 0; mt < 2; mt++)
                MMA_TF32(acc[mt][nt], al[mt][0], al[mt][1], al[mt][2], al[mt][3], bw[nt].x, bw[nt].y);
        // pass 3: hi*lo
        #pragma unroll
        for (int nt = 0; nt < NTW; nt++)
            #pragma unroll
            for (int mt = 0; mt < 2; mt++)
                MMA_TF32(acc[mt][nt], ah[mt][0], ah[mt][1], ah[mt][2], ah[mt][3], bw[nt].z, bw[nt].w);
    }

    // ---- epilogue: H stores + a_src/a_dst logit dots ----
    float sp[2][2], dp[2][2];
    #pragma unroll
    for (int mt = 0; mt < 2; mt++)
        sp[mt][0] = sp[mt][1] = dp[mt][0] = dp[mt][1] = 0.f;

    #pragma unroll
    for (int mt = 0; mt < 2; mt++) {
        int rA = m0 + wm * 32 + mt * 16 + lr;
        int rB = rA + 8;
        #pragma unroll
        for (int nt = 0; nt < NTW; nt++) {
            int c = (wn * NTW + nt) * 8 + kq * 2;
            float s0 = __ldg(&avs[c]), s1 = __ldg(&avs[c + 1]);
            float d0 = __ldg(&avd[c]), d1 = __ldg(&avd[c + 1]);
            sp[mt][0] += acc[mt][nt][0] * s0 + acc[mt][nt][1] * s1;
            dp[mt][0] += acc[mt][nt][0] * d0 + acc[mt][nt][1] * d1;
            sp[mt][1] += acc[mt][nt][2] * s0 + acc[mt][nt][3] * s1;
            dp[mt][1] += acc[mt][nt][2] * d0 + acc[mt][nt][3] * d1;
            if (rA < NN)
                *(float2*)&H[(size_t)rA * BN + c] = make_float2(acc[mt][nt][0], acc[mt][nt][1]);
            if (rB < NN)
                *(float2*)&H[(size_t)rB * BN + c] = make_float2(acc[mt][nt][2], acc[mt][nt][3]);
        }
    }
    #pragma unroll
    for (int o = 1; o <= 2; o <<= 1)
        #pragma unroll
        for (int mt = 0; mt < 2; mt++) {
            sp[mt][0] += __shfl_xor_sync(0xffffffffu, sp[mt][0], o);
            dp[mt][0] += __shfl_xor_sync(0xffffffffu, dp[mt][0], o);
            sp[mt][1] += __shfl_xor_sync(0xffffffffu, sp[mt][1], o);
            dp[mt][1] += __shfl_xor_sync(0xffffffffu, dp[mt][1], o);
        }

    __syncthreads();                 // smem reuse: ep[BM][4][2]
    float* ep = sm;
    if (kq == 0) {
        #pragma unroll
        for (int mt = 0; mt < 2; mt++) {
            int r0 = wm * 32 + mt * 16 + lr;
            ep[(r0 * 4 + wn) * 2 + 0]       = sp[mt][0];
            ep[(r0 * 4 + wn) * 2 + 1]       = dp[mt][0];
            ep[((r0 + 8) * 4 + wn) * 2 + 0] = sp[mt][1];
            ep[((r0 + 8) * 4 + wn) * 2 + 1] = dp[mt][1];
        }
    }
    __syncthreads();
    if (tid < BM && m0 + tid < NN) {
        float s = 0.f, d = 0.f;
        #pragma unroll
        for (int w = 0; w < 4; w++) {
            s += ep[(tid * 4 + w) * 2 + 0];
            d += ep[(tid * 4 + w) * 2 + 1];
        }
        g_as[m0 + tid] = s;
        g_ad[m0 + tid] = d;
    }
}

// ---------------- warp-per-row single-pass GAT aggregation ----------------
template <int D, bool ADD_BIAS>
__global__ __launch_bounds__(256) void aggregate(
    const float* __restrict__ H, const float* __restrict__ bias,
    float* __restrict__ OUT)
{
    constexpr int V = D / 32;
    int row = blockIdx.x * 8 + (threadIdx.x >> 5);
    if (row >= NN) return;
    int lane = threadIdx.x & 31;
    int beg = g_rowptr[row], end = g_rowptr[row + 1];
    float ad_r = g_ad[row];

    float den = 0.f;
    float acc[V];
    #pragma unroll
    for (int v = 0; v < V; v++) acc[v] = 0.f;

    for (int base = beg; base < end; base += 32) {
        int n = min(32, end - base);
        int s = 0; float ex = 0.f;
        if (lane < n) {
            s = __ldg(&g_colsrc[base + lane]);
            float e = __ldg(&g_as[s]) + ad_r;
            e = e > 0.f ? e : 0.2f * e;
            ex = __expf(e);
            den += ex;
        }
        #pragma unroll 4
        for (int j = 0; j < n; j++) {
            int   sj = __shfl_sync(0xffffffffu, s, j);
            float wj = __shfl_sync(0xffffffffu, ex, j);
            const float* hp = H + (size_t)sj * D + lane * V;
            if constexpr (V == 4) {
                float4 h = __ldg((const float4*)hp);
                acc[0] = fmaf(wj, h.x, acc[0]);
                acc[1] = fmaf(wj, h.y, acc[1]);
                acc[2] = fmaf(wj, h.z, acc[2]);
                acc[3] = fmaf(wj, h.w, acc[3]);
            } else {
                float2 h = __ldg((const float2*)hp);
                acc[0] = fmaf(wj, h.x, acc[0]);
                acc[1] = fmaf(wj, h.y, acc[1]);
            }
        }
    }

    #pragma unroll
    for (int o = 16; o; o >>= 1) den += __shfl_xor_sync(0xffffffffu, den, o);
    float inv = 1.f / (den + 1e-16f);

    float* op = OUT + (size_t)row * D + lane * V;
    if constexpr (ADD_BIAS) {
        #pragma unroll
        for (int v = 0; v < V; v++) acc[v] = fmaf(acc[v], inv, bias[lane * V + v]);
    } else {
        #pragma unroll
        for (int v = 0; v < V; v++) acc[v] *= inv;
    }
    if constexpr (V == 4)
        *(float4*)op = make_float4(acc[0], acc[1], acc[2], acc[3]);
    else
        *(float2*)op = make_float2(acc[0], acc[1]);
}

// ---------------- launch (two-stream fork/join, capture-legal) ----------
extern "C" void kernel_launch(void* const* d_in, const int* in_sizes, int n_in,
                              void* d_out, int out_size) {
    const float* x   = (const float*)d_in[0];
    const void*  ei  = d_in[1];
    const float* W1  = (const float*)d_in[2];
    const float* as1 = (const float*)d_in[3];
    const float* ad1 = (const float*)d_in[4];
    const float* b1  = (const float*)d_in[5];
    const float* W2  = (const float*)d_in[6];
    const float* as2 = (const float*)d_in[7];
    const float* ad2 = (const float*)d_in[8];
    const float* b2  = (const float*)d_in[9];
    float* out = (float*)d_out;

    float *p_h1, *p_out1, *p_h2;
    int   *p_deg;
    uint32_t *p_wf1, *p_wf2;
    cudaGetSymbolAddress((void**)&p_h1,   g_h1);
    cudaGetSymbolAddress((void**)&p_out1, g_out1);
    cudaGetSymbolAddress((void**)&p_h2,   g_h2);
    cudaGetSymbolAddress((void**)&p_deg,  g_deg);
    cudaGetSymbolAddress((void**)&p_wf1,  g_wf1);
    cudaGetSymbolAddress((void**)&p_wf2,  g_wf2);

    const int SMEM = 2 * 64 * 132 * 4;   // 67,584 B (both layers)
    cudaFuncSetAttribute(gemm_tc<128, false>,
                         cudaFuncAttributeMaxDynamicSharedMemorySize, SMEM);
    cudaFuncSetAttribute(gemm_tc<64, true>,
                         cudaFuncAttributeMaxDynamicSharedMemorySize, SMEM);

    const int nblk = (NN + 1023) / 1024;   // 98
    const int gblocks = (NN + 63) / 64;    // 1563

    // Fork a second stream so the CSR build hides under gemm1.
    // Create/destroy paired inside the call: no persistent state, no leak,
    // mem-checkpoint neutral. Standard capture fork/join via events.
    cudaStream_t sB;
    cudaStreamCreateWithFlags(&sB, cudaStreamNonBlocking);
    cudaEvent_t evFork, evJoin;
    cudaEventCreateWithFlags(&evFork, cudaEventDisableTiming);
    cudaEventCreateWithFlags(&evJoin, cudaEventDisableTiming);

    // origin stream: dtype sniff (needed by both branches)
    detect_edge_dtype<<<1, 32>>>((const int*)ei);
    cudaEventRecord(evFork, 0);
    cudaStreamWaitEvent(sB, evFork, 0);

    // stream B: CSR build (independent of gemm chain)
    cudaMemsetAsync(p_deg, 0, NN * sizeof(int), sB);
    histo_edges<<<(EE + 255) / 256, 256, 0, sB>>>(ei);
    scan1<<<nblk, 1024, 0, sB>>>();
    scan2<<<1, 128, 0, sB>>>(nblk);
    scan3<<<(NN + 256) / 256, 256, 0, sB>>>();
    fill_csr<<<(EE + 255) / 256, 256, 0, sB>>>(ei);
    cudaEventRecord(evJoin, sB);

    // origin stream: GEMM chain (overlaps CSR build)
    prep_w<<<(16 * 16 * 32 + 255) / 256, 256>>>(W1, p_wf1, 16);
    gemm_tc<128, false><<<gblocks, 256, SMEM>>>(x, p_wf1, nullptr, as1, ad1, p_h1);
    prep_w<<<(16 * 8 * 32 + 255) / 256, 256>>>(W2, p_wf2, 8);

    // join: aggregate needs both CSR and gemm1
    cudaStreamWaitEvent(0, evJoin, 0);
    aggregate<128, false><<<(NN + 7) / 8, 256>>>(p_h1, nullptr, p_out1);
    gemm_tc<64, true><<<gblocks, 256, SMEM>>>(p_out1, p_wf2, b1, as2, ad2, p_h2);
    aggregate<64, true><<<(NN + 7) / 8, 256>>>(p_h2, b2, out);

    cudaEventDestroy(evFork);
    cudaEventDestroy(evJoin);
    cudaStreamDestroy(sB);
}

// round 13
// speedup vs baseline: 1.3141x; 1.0319x over previous
#include <cuda_runtime.h>
#include <cstdint>

#define NN 100000
#define EE 1600000

// ---------------- scratch (no allocations allowed) ----------------
__device__ float g_h1[(size_t)NN * 128];
__device__ float g_out1[(size_t)NN * 128];
__device__ float g_h2[(size_t)NN * 64];
__device__ float g_as[NN];
__device__ float g_ad[NN];
__device__ int   g_deg[NN];
__device__ int   g_rowptr[NN + 1];
__device__ int   g_cursor[NN];
__device__ int   g_bsum[128];
__device__ int   g_colsrc[EE];
__device__ int   g_is64;
__device__ uint32_t g_wf1[16 * 16 * 32 * 4];   // W1 fragments (hi/lo tf32)
__device__ uint32_t g_wf2[16 * 8 * 32 * 4];    // W2 fragments

// ---------------- edge dtype sniff ----------------
__global__ void detect_edge_dtype(const int* __restrict__ ei32) {
    if (threadIdx.x == 0 && blockIdx.x == 0) {
        int all_hi_zero = 1;
        for (int i = 0; i < 256; i++)
            if (ei32[2 * i + 1] != 0) { all_hi_zero = 0; break; }
        g_is64 = all_hi_zero;
    }
}

__device__ __forceinline__ int load_edge(const void* ei, int i, int half) {
    int v;
    if (g_is64) v = (int)((const long long*)ei)[(size_t)half * EE + i];
    else        v = ((const int*)ei)[(size_t)half * EE + i];
    return min(max(v, 0), NN - 1);
}

__global__ __launch_bounds__(256) void histo_edges(const void* __restrict__ ei) {
    int i = blockIdx.x * 256 + threadIdx.x;
    if (i >= EE) return;
    atomicAdd(&g_deg[load_edge(ei, i, 1)], 1);
}

// ---------------- exclusive scan ----------------
__global__ __launch_bounds__(1024) void scan1() {
    __shared__ int sh[1024];
    int i = blockIdx.x * 1024 + threadIdx.x;
    int v = (i < NN) ? g_deg[i] : 0;
    sh[threadIdx.x] = v;
    __syncthreads();
    #pragma unroll
    for (int o = 1; o < 1024; o <<= 1) {
        int t = (threadIdx.x >= o) ? sh[threadIdx.x - o] : 0;
        __syncthreads();
        sh[threadIdx.x] += t;
        __syncthreads();
    }
    if (i < NN) g_rowptr[i] = sh[threadIdx.x] - v;
    if (threadIdx.x == 1023) g_bsum[blockIdx.x] = sh[1023];
}

__global__ void scan2(int nblk) {
    __shared__ int sh[128];
    int v = (threadIdx.x < nblk) ? g_bsum[threadIdx.x] : 0;
    sh[threadIdx.x] = v;
    __syncthreads();
    #pragma unroll
    for (int o = 1; o < 128; o <<= 1) {
        int t = (threadIdx.x >= o) ? sh[threadIdx.x - o] : 0;
        __syncthreads();
        sh[threadIdx.x] += t;
        __syncthreads();
    }
    if (threadIdx.x < nblk) g_bsum[threadIdx.x] = sh[threadIdx.x] - v;
}

__global__ __launch_bounds__(256) void scan3() {
    int i = blockIdx.x * 256 + threadIdx.x;
    if (i < NN) {
        int rp = g_rowptr[i] + g_bsum[i >> 10];
        g_rowptr[i] = rp;
        g_cursor[i] = rp;
    }
    if (i == NN) g_rowptr[NN] = EE;
}

__global__ __launch_bounds__(256) void fill_csr(const void* __restrict__ ei) {
    int e = blockIdx.x * 256 + threadIdx.x;
    if (e >= EE) return;
    int s = load_edge(ei, e, 0);
    int d = load_edge(ei, e, 1);
    int pos = atomicAdd(&g_cursor[d], 1);
    g_colsrc[pos] = s;
}

// ---------------- tf32 helpers ----------------
__device__ __forceinline__ uint32_t f2tf32(float x) {
    uint32_t r;
    asm("cvt.rna.tf32.f32 %0, %1;" : "=r"(r) : "f"(x));
    return r;
}
__device__ __forceinline__ uint32_t tf32lo(float x, uint32_t hi) {
    return f2tf32(x - __uint_as_float(hi));
}

#define MMA_TF32(d, a0, a1, a2, a3, b0, b1)                                \
    asm volatile("mma.sync.aligned.m16n8k8.row.col.f32.tf32.tf32.f32 "     \
        "{%0,%1,%2,%3}, {%4,%5,%6,%7}, {%8,%9}, {%0,%1,%2,%3};"            \
        : "+f"(d[0]), "+f"(d[1]), "+f"(d[2]), "+f"(d[3])                   \
        : "r"(a0), "r"(a1), "r"(a2), "r"(a3), "r"(b0), "r"(b1))

// ---------------- W fragment prep (once per layer) ----------------
__global__ __launch_bounds__(256) void prep_w(const float* __restrict__ W,
                                              uint32_t* __restrict__ wf,
                                              int N8) {
    int t = blockIdx.x * 256 + threadIdx.x;
    if (t >= 16 * N8 * 32) return;
    int lane = t & 31;
    int n8 = (t >> 5) % N8;
    int k8 = (t >> 5) / N8;
    int lr = lane >> 2, kq = lane & 3;
    int N = N8 * 8;
    float w0 = W[(size_t)(k8 * 8 + kq)     * N + n8 * 8 + lr];
    float w1 = W[(size_t)(k8 * 8 + kq + 4) * N + n8 * 8 + lr];
    uint32_t h0 = f2tf32(w0), h1 = f2tf32(w1);
    uint4 v = make_uint4(h0, h1, tf32lo(w0, h0), tf32lo(w1, h1));
    ((uint4*)wf)[t] = v;
}

// ---------------- tensor-core GEMM (3xTF32, K chunked for occupancy) ----
// 256 threads: 8 warps = 2 m-slabs x 4 n-groups, NTW=BN/32 n-tiles/warp.
// K processed in 2 chunks of 64 -> A smem halves (34.8KB) -> 6 blocks/SM.
// k8 order 0..7 then 8..15 with identical per-acc MMA sequence ->
// bitwise-identical numerics to R11/R12 (rel_err 1.786e-6).
template <int BN, bool RELU_BIAS>
__global__ __launch_bounds__(256) void gemm_tc(
    const float* __restrict__ X, const uint32_t* __restrict__ WF,
    const float* __restrict__ bin,
    const float* __restrict__ avs, const float* __restrict__ avd,
    float* __restrict__ H)
{
    constexpr int K = 128, BM = 64, KC = 64, KP = 68;  // 68 % 32 = 4: conflict-free
    constexpr int N8 = BN / 8;       // 16 or 8
    constexpr int NTW = BN / 32;     // n-tiles per warp: 4 or 2
    constexpr int THREADS = 256;

    extern __shared__ float sm[];
    float* AsH = sm;                 // [BM][KP]
    float* AsL = sm + BM * KP;       // [BM][KP]

    const int tid = threadIdx.x, lane = tid & 31, wid = tid >> 5;
    const int wm = wid & 1, wn = wid >> 1;       // wn in 0..3
    const int m0 = blockIdx.x * BM;
    const int lr = lane >> 2, kq = lane & 3;

    float acc[2][NTW][4];
    #pragma unroll
    for (int mt = 0; mt < 2; mt++)
        #pragma unroll
        for (int nt = 0; nt < NTW; nt++)
            #pragma unroll
            for (int c = 0; c < 4; c++) acc[mt][nt][c] = 0.f;

    const uint4* wf = (const uint4*)WF;

    #pragma unroll
    for (int kc = 0; kc < 2; kc++) {
        if (kc) __syncthreads();     // protect smem reuse across chunks
        // ---- stage A chunk: load, (bias+relu), split hi/lo ----
        #pragma unroll
        for (int it = tid; it < BM * (KC / 4); it += THREADS) {
            int r = it >> 4, c4 = it & 15;
            float4 v = make_float4(0.f, 0.f, 0.f, 0.f);
            if (m0 + r < NN) {
                v = ((const float4*)X)[(size_t)(m0 + r) * (K / 4) + kc * (KC / 4) + c4];
                if constexpr (RELU_BIAS) {
                    float4 bb = ((const float4*)bin)[kc * (KC / 4) + c4];
                    v.x = fmaxf(v.x + bb.x, 0.f);
                    v.y = fmaxf(v.y + bb.y, 0.f);
                    v.z = fmaxf(v.z + bb.z, 0.f);
                    v.w = fmaxf(v.w + bb.w, 0.f);
                }
            }
            uint32_t hx = f2tf32(v.x), hy = f2tf32(v.y);
            uint32_t hz = f2tf32(v.z), hw = f2tf32(v.w);
            *(uint4*)&AsH[r * KP + c4 * 4] = make_uint4(hx, hy, hz, hw);
            *(uint4*)&AsL[r * KP + c4 * 4] =
                make_uint4(tf32lo(v.x, hx), tf32lo(v.y, hy),
                           tf32lo(v.z, hz), tf32lo(v.w, hw));
        }
        __syncthreads();

        // ---- mainloop: LDS.32 (A) + LDG.128 (B) + interleaved MMA passes ----
        #pragma unroll
        for (int k8 = 0; k8 < 8; k8++) {
            int k8g = kc * 8 + k8;   // global k8 for W fragments
            int k0 = k8 * 8;         // local k offset in chunk
            uint4 bw[NTW];
            #pragma unroll
            for (int nt = 0; nt < NTW; nt++)
                bw[nt] = wf[(size_t)(k8g * N8 + wn * NTW + nt) * 32 + lane];

            uint32_t ah[2][4], al[2][4];
            #pragma unroll
            for (int mt = 0; mt < 2; mt++) {
                int base = (wm * 32 + mt * 16 + lr) * KP + k0 + kq;
                ah[mt][0] = *(const uint32_t*)&AsH[base];
                ah[mt][1] = *(const uint32_t*)&AsH[base + 8 * KP];
                ah[mt][2] = *(const uint32_t*)&AsH[base + 4];
                ah[mt][3] = *(const uint32_t*)&AsH[base + 8 * KP + 4];
                al[mt][0] = *(const uint32_t*)&AsL[base];
                al[mt][1] = *(const uint32_t*)&AsL[base + 8 * KP];
                al[mt][2] = *(const uint32_t*)&AsL[base + 4];
                al[mt][3] = *(const uint32_t*)&AsL[base + 8 * KP + 4];
            }
            // pass 1: hi*hi across all tiles
            #pragma unroll
            for (int nt = 0; nt < NTW; nt++)
                #pragma unroll
                for (int mt = 0; mt < 2; mt++)
                    MMA_TF32(acc[mt][nt], ah[mt][0], ah[mt][1], ah[mt][2], ah[mt][3], bw[nt].x, bw[nt].y);
            // pass 2: lo*hi
            #pragma unroll
            for (int nt = 0; nt < NTW; nt++)
                #pragma unroll
                for (int mt = 0; mt < 2; mt++)
                    MMA_TF32(acc[mt][nt], al[mt][0], al[mt][1], al[mt][2], al[mt][3], bw[nt].x, bw[nt].y);
            // pass 3: hi*lo
            #pragma unroll
            for (int nt = 0; nt < NTW; nt++)
                #pragma unroll
                for (int mt = 0; mt < 2; mt++)
                    MMA_TF32(acc[mt][nt], ah[mt][0], ah[mt][1], ah[mt][2], ah[mt][3], bw[nt].z, bw[nt].w);
        }
    }

    // ---- epilogue: H stores + a_src/a_dst logit dots ----
    float sp[2][2], dp[2][2];
    #pragma unroll
    for (int mt = 0; mt < 2; mt++)
        sp[mt][0] = sp[mt][1] = dp[mt][0] = dp[mt][1] = 0.f;

    #pragma unroll
    for (int mt = 0; mt < 2; mt++) {
        int rA = m0 + wm * 32 + mt * 16 + lr;
        int rB = rA + 8;
        #pragma unroll
        for (int nt = 0; nt < NTW; nt++) {
            int c = (wn * NTW + nt) * 8 + kq * 2;
            float s0 = __ldg(&avs[c]), s1 = __ldg(&avs[c + 1]);
            float d0 = __ldg(&avd[c]), d1 = __ldg(&avd[c + 1]);
            sp[mt][0] += acc[mt][nt][0] * s0 + acc[mt][nt][1] * s1;
            dp[mt][0] += acc[mt][nt][0] * d0 + acc[mt][nt][1] * d1;
            sp[mt][1] += acc[mt][nt][2] * s0 + acc[mt][nt][3] * s1;
            dp[mt][1] += acc[mt][nt][2] * d0 + acc[mt][nt][3] * d1;
            if (rA < NN)
                *(float2*)&H[(size_t)rA * BN + c] = make_float2(acc[mt][nt][0], acc[mt][nt][1]);
            if (rB < NN)
                *(float2*)&H[(size_t)rB * BN + c] = make_float2(acc[mt][nt][2], acc[mt][nt][3]);
        }
    }
    #pragma unroll
    for (int o = 1; o <= 2; o <<= 1)
        #pragma unroll
        for (int mt = 0; mt < 2; mt++) {
            sp[mt][0] += __shfl_xor_sync(0xffffffffu, sp[mt][0], o);
            dp[mt][0] += __shfl_xor_sync(0xffffffffu, dp[mt][0], o);
            sp[mt][1] += __shfl_xor_sync(0xffffffffu, sp[mt][1], o);
            dp[mt][1] += __shfl_xor_sync(0xffffffffu, dp[mt][1], o);
        }

    __syncthreads();                 // smem reuse: ep[BM][4][2]
    float* ep = sm;
    if (kq == 0) {
        #pragma unroll
        for (int mt = 0; mt < 2; mt++) {
            int r0 = wm * 32 + mt * 16 + lr;
            ep[(r0 * 4 + wn) * 2 + 0]       = sp[mt][0];
            ep[(r0 * 4 + wn) * 2 + 1]       = dp[mt][0];
            ep[((r0 + 8) * 4 + wn) * 2 + 0] = sp[mt][1];
            ep[((r0 + 8) * 4 + wn) * 2 + 1] = dp[mt][1];
        }
    }
    __syncthreads();
    if (tid < BM && m0 + tid < NN) {
        float s = 0.f, d = 0.f;
        #pragma unroll
        for (int w = 0; w < 4; w++) {
            s += ep[(tid * 4 + w) * 2 + 0];
            d += ep[(tid * 4 + w) * 2 + 1];
        }
        g_as[m0 + tid] = s;
        g_ad[m0 + tid] = d;
    }
}

// ---------------- warp-per-row single-pass GAT aggregation ----------------
template <int D, bool ADD_BIAS>
__global__ __launch_bounds__(256) void aggregate(
    const float* __restrict__ H, const float* __restrict__ bias,
    float* __restrict__ OUT)
{
    constexpr int V = D / 32;
    int row = blockIdx.x * 8 + (threadIdx.x >> 5);
    if (row >= NN) return;
    int lane = threadIdx.x & 31;
    int beg = g_rowptr[row], end = g_rowptr[row + 1];
    float ad_r = g_ad[row];

    float den = 0.f;
    float acc[V];
    #pragma unroll
    for (int v = 0; v < V; v++) acc[v] = 0.f;

    for (int base = beg; base < end; base += 32) {
        int n = min(32, end - base);
        int s = 0; float ex = 0.f;
        if (lane < n) {
            s = __ldg(&g_colsrc[base + lane]);
            float e = __ldg(&g_as[s]) + ad_r;
            e = e > 0.f ? e : 0.2f * e;
            ex = __expf(e);
            den += ex;
        }
        #pragma unroll 4
        for (int j = 0; j < n; j++) {
            int   sj = __shfl_sync(0xffffffffu, s, j);
            float wj = __shfl_sync(0xffffffffu, ex, j);
            const float* hp = H + (size_t)sj * D + lane * V;
            if constexpr (V == 4) {
                float4 h = __ldg((const float4*)hp);
                acc[0] = fmaf(wj, h.x, acc[0]);
                acc[1] = fmaf(wj, h.y, acc[1]);
                acc[2] = fmaf(wj, h.z, acc[2]);
                acc[3] = fmaf(wj, h.w, acc[3]);
            } else {
                float2 h = __ldg((const float2*)hp);
                acc[0] = fmaf(wj, h.x, acc[0]);
                acc[1] = fmaf(wj, h.y, acc[1]);
            }
        }
    }

    #pragma unroll
    for (int o = 16; o; o >>= 1) den += __shfl_xor_sync(0xffffffffu, den, o);
    float inv = 1.f / (den + 1e-16f);

    float* op = OUT + (size_t)row * D + lane * V;
    if constexpr (ADD_BIAS) {
        #pragma unroll
        for (int v = 0; v < V; v++) acc[v] = fmaf(acc[v], inv, bias[lane * V + v]);
    } else {
        #pragma unroll
        for (int v = 0; v < V; v++) acc[v] *= inv;
    }
    if constexpr (V == 4)
        *(float4*)op = make_float4(acc[0], acc[1], acc[2], acc[3]);
    else
        *(float2*)op = make_float2(acc[0], acc[1]);
}

// ---------------- launch (two-stream fork/join, capture-legal) ----------
extern "C" void kernel_launch(void* const* d_in, const int* in_sizes, int n_in,
                              void* d_out, int out_size) {
    const float* x   = (const float*)d_in[0];
    const void*  ei  = d_in[1];
    const float* W1  = (const float*)d_in[2];
    const float* as1 = (const float*)d_in[3];
    const float* ad1 = (const float*)d_in[4];
    const float* b1  = (const float*)d_in[5];
    const float* W2  = (const float*)d_in[6];
    const float* as2 = (const float*)d_in[7];
    const float* ad2 = (const float*)d_in[8];
    const float* b2  = (const float*)d_in[9];
    float* out = (float*)d_out;

    float *p_h1, *p_out1, *p_h2;
    int   *p_deg;
    uint32_t *p_wf1, *p_wf2;
    cudaGetSymbolAddress((void**)&p_h1,   g_h1);
    cudaGetSymbolAddress((void**)&p_out1, g_out1);
    cudaGetSymbolAddress((void**)&p_h2,   g_h2);
    cudaGetSymbolAddress((void**)&p_deg,  g_deg);
    cudaGetSymbolAddress((void**)&p_wf1,  g_wf1);
    cudaGetSymbolAddress((void**)&p_wf2,  g_wf2);

    const int SMEM = 2 * 64 * 68 * 4;   // 34,816 B (both layers)
    cudaFuncSetAttribute(gemm_tc<128, false>,
                         cudaFuncAttributeMaxDynamicSharedMemorySize, SMEM);
    cudaFuncSetAttribute(gemm_tc<64, true>,
                         cudaFuncAttributeMaxDynamicSharedMemorySize, SMEM);

    const int nblk = (NN + 1023) / 1024;   // 98
    const int gblocks = (NN + 63) / 64;    // 1563

    // Fork a second stream so the CSR build hides under gemm1.
    cudaStream_t sB;
    cudaStreamCreateWithFlags(&sB, cudaStreamNonBlocking);
    cudaEvent_t evFork, evJoin;
    cudaEventCreateWithFlags(&evFork, cudaEventDisableTiming);
    cudaEventCreateWithFlags(&evJoin, cudaEventDisableTiming);

    // origin stream: dtype sniff (needed by both branches)
    detect_edge_dtype<<<1, 32>>>((const int*)ei);
    cudaEventRecord(evFork, 0);
    cudaStreamWaitEvent(sB, evFork, 0);

    // stream B: CSR build (independent of gemm chain)
    cudaMemsetAsync(p_deg, 0, NN * sizeof(int), sB);
    histo_edges<<<(EE + 255) / 256, 256, 0, sB>>>(ei);
    scan1<<<nblk, 1024, 0, sB>>>();
    scan2<<<1, 128, 0, sB>>>(nblk);
    scan3<<<(NN + 256) / 256, 256, 0, sB>>>();
    fill_csr<<<(EE + 255) / 256, 256, 0, sB>>>(ei);
    cudaEventRecord(evJoin, sB);

    // origin stream: GEMM chain (overlaps CSR build)
    prep_w<<<(16 * 16 * 32 + 255) / 256, 256>>>(W1, p_wf1, 16);
    gemm_tc<128, false><<<gblocks, 256, SMEM>>>(x, p_wf1, nullptr, as1, ad1, p_h1);
    prep_w<<<(16 * 8 * 32 + 255) / 256, 256>>>(W2, p_wf2, 8);

    // join: aggregate needs both CSR and gemm1
    cudaStreamWaitEvent(0, evJoin, 0);
    aggregate<128, false><<<(NN + 7) / 8, 256>>>(p_h1, nullptr, p_out1);
    gemm_tc<64, true><<<gblocks, 256, SMEM>>>(p_out1, p_wf2, b1, as2, ad2, p_h2);
    aggregate<64, true><<<(NN + 7) / 8, 256>>>(p_h2, b2, out);

    cudaEventDestroy(evFork);
    cudaEventDestroy(evJoin);
    cudaStreamDestroy(sB);
}